// round 7
// baseline (speedup 1.0000x reference)
#include <cuda_runtime.h>

// Problem constants
#define B_   16
#define C_   512
#define N_   4096
#define M_   2048
#define TQ   32      // tokens per CTA
#define MC   64      // memory rows per chunk
#define QP   516     // padded smem row stride (floats) for qs/ks
#define STQ  36      // padded stride for transposed score tile St[MC][STQ]
#define NCHUNK (M_ / MC)
#define NTHREADS 256

// smem (floats): qs[TQ][QP] + ks[MC][QP] + St[MC][STQ] + Sp[MC][STQ] + m/l/sc[TQ each]
#define SMEM_FLOATS (TQ*QP + MC*QP + 2*MC*STQ + 3*TQ)

typedef unsigned long long ull;

__device__ __forceinline__ ull fma2(ull a, ull b, ull c) {
    ull d;
    asm("fma.rn.f32x2 %0, %1, %2, %3;" : "=l"(d) : "l"(a), "l"(b), "l"(c));
    return d;
}
__device__ __forceinline__ ull mul2(ull a, ull b) {
    ull d;
    asm("mul.rn.f32x2 %0, %1, %2;" : "=l"(d) : "l"(a), "l"(b));
    return d;
}
__device__ __forceinline__ ull pack2(float x, float y) {
    ull d;
    asm("mov.b64 %0, {%1, %2};" : "=l"(d) : "f"(x), "f"(y));
    return d;
}
__device__ __forceinline__ void unpack2(ull d, float& x, float& y) {
    asm("mov.b64 {%0, %1}, %2;" : "=f"(x), "=f"(y) : "l"(d));
}

__global__ __launch_bounds__(NTHREADS, 1)
void memattn_fused_f32x2(const float* __restrict__ feat,
                         const float* __restrict__ mem,
                         float* __restrict__ out)
{
    extern __shared__ float smem[];
    float* qs   = smem;                 // TQ*QP
    float* ks   = qs + TQ * QP;         // MC*QP
    float* St   = ks + MC * QP;         // MC*STQ  (scores, transposed: [mrow][tok])
    float* Sp   = St + MC * STQ;        // MC*STQ  (k-split partials, same layout)
    float* m_s  = Sp + MC * STQ;        // TQ
    float* l_s  = m_s + TQ;             // TQ
    float* sc_s = l_s + TQ;             // TQ

    const int t    = threadIdx.x;
    const int lane = t & 31;
    const int b    = blockIdx.y;
    const int n0   = blockIdx.x * TQ;

    if (t < TQ) { m_s[t] = -3.0e38f; l_s[t] = 0.0f; }

    // ---- load Q tile: qs[tok][c] = feat[b, c, n0+tok] (coalesced over tok) ----
    const float* fbase = feat + (size_t)b * C_ * N_ + n0;
    #pragma unroll 4
    for (int idx = t; idx < TQ * C_; idx += NTHREADS) {
        int tok = idx & (TQ - 1);
        int c   = idx >> 5;
        qs[tok * QP + c] = fbase[(size_t)c * N_ + tok];
    }

    // ---- GEMM1 mapping: 2-way k-split; within-warp tg spans 4, mg spans 8 ----
    const int kid   = t >> 7;                                   // 0..1
    const int warp5 = (t & 127) >> 5;                           // 0..3
    const int tg    = ((warp5 & 1) << 2) | ((lane >> 3) & 3);   // 0..7  -> tokens tg*4..+3
    const int mg    = ((warp5 >> 1) << 3) | (lane & 7);         // 0..15 -> mrows mg+16*j

    // ---- GEMM2 mapping: warp owns 64-col block; lane: tokg (8) x colg (4) ----
    const int tokg  = lane >> 2;                                // 0..7 -> tokens tokg*4..+3
    const int cbase = (t >> 5) * 64 + (lane & 3) * 4;           // cols cbase + 16*i + {0..3}

    ull O2[4][8];                                               // [token][col-pair]
    #pragma unroll
    for (int a = 0; a < 4; a++)
        #pragma unroll
        for (int c = 0; c < 8; c++) O2[a][c] = 0ull;

    for (int ch = 0; ch < NCHUNK; ch++) {
        __syncthreads();   // prev GEMM2 done with ks/St (and q-load on ch==0)

        // ---- load K chunk (MC x C) into ks ----
        const float* mbase = mem + (size_t)(ch * MC) * C_;
        #pragma unroll 4
        for (int idx = t; idx < MC * (C_ / 4); idx += NTHREADS) {
            int row = idx >> 7;
            int c4  = idx & 127;
            float4 v = *(const float4*)(mbase + (size_t)row * C_ + c4 * 4);
            *(float4*)(ks + row * QP + c4 * 4) = v;
        }
        __syncthreads();

        // ---- GEMM1: S = Q @ K^T, packed f32x2, 2-way k-split ----
        ull acc2[4][4];
        #pragma unroll
        for (int i = 0; i < 4; i++)
            #pragma unroll
            for (int j = 0; j < 4; j++) acc2[i][j] = 0ull;

        const int kbeg = kid * 256;
        #pragma unroll 2
        for (int k = kbeg; k < kbeg + 256; k += 4) {
            ulonglong2 qv[4], kv[4];
            #pragma unroll
            for (int i = 0; i < 4; i++)
                qv[i] = *(const ulonglong2*)(qs + (tg * 4 + i) * QP + k);
            #pragma unroll
            for (int j = 0; j < 4; j++)
                kv[j] = *(const ulonglong2*)(ks + (mg + 16 * j) * QP + k);
            #pragma unroll
            for (int i = 0; i < 4; i++)
                #pragma unroll
                for (int j = 0; j < 4; j++) {
                    acc2[i][j] = fma2(qv[i].x, kv[j].x, acc2[i][j]);
                    acc2[i][j] = fma2(qv[i].y, kv[j].y, acc2[i][j]);
                }
        }

        if (kid == 1) {
            #pragma unroll
            for (int i = 0; i < 4; i++)
                #pragma unroll
                for (int j = 0; j < 4; j++) {
                    float lo, hi; unpack2(acc2[i][j], lo, hi);
                    Sp[(mg + 16 * j) * STQ + tg * 4 + i] = lo + hi;
                }
        }
        __syncthreads();
        if (kid == 0) {
            #pragma unroll
            for (int i = 0; i < 4; i++)
                #pragma unroll
                for (int j = 0; j < 4; j++) {
                    float lo, hi; unpack2(acc2[i][j], lo, hi);
                    int off = (mg + 16 * j) * STQ + tg * 4 + i;
                    St[off] = lo + hi + Sp[off];
                }
        }
        __syncthreads();

        // ---- online softmax on St columns (per token), 8 lanes/token ----
        {
            int row = t >> 3;          // token
            int g   = t & 7;
            float mx = -3.0e38f;
            #pragma unroll
            for (int j = g; j < MC; j += 8) mx = fmaxf(mx, St[j * STQ + row]);
            mx = fmaxf(mx, __shfl_xor_sync(0xffffffffu, mx, 4));
            mx = fmaxf(mx, __shfl_xor_sync(0xffffffffu, mx, 2));
            mx = fmaxf(mx, __shfl_xor_sync(0xffffffffu, mx, 1));
            float oldm = m_s[row];
            float newm = fmaxf(oldm, mx);
            float sum = 0.0f;
            #pragma unroll
            for (int j = g; j < MC; j += 8) {
                float p = __expf(St[j * STQ + row] - newm);
                St[j * STQ + row] = p;
                sum += p;
            }
            sum += __shfl_xor_sync(0xffffffffu, sum, 4);
            sum += __shfl_xor_sync(0xffffffffu, sum, 2);
            sum += __shfl_xor_sync(0xffffffffu, sum, 1);
            if (g == 0) {
                float sc = __expf(oldm - newm);
                sc_s[row] = sc;
                m_s[row]  = newm;
                l_s[row]  = l_s[row] * sc + sum;
            }
        }
        __syncthreads();

        // ---- GEMM2: O += P @ K (packed f32x2, rescale-then-accumulate) ----
        #pragma unroll
        for (int tt = 0; tt < 4; tt++) {
            float sc = sc_s[tokg * 4 + tt];
            ull sc2 = pack2(sc, sc);
            #pragma unroll
            for (int c = 0; c < 8; c++) O2[tt][c] = mul2(O2[tt][c], sc2);
        }
        #pragma unroll 4
        for (int j = 0; j < MC; j++) {
            float4 pf = *(const float4*)(St + j * STQ + tokg * 4);
            ull p2[4];
            p2[0] = pack2(pf.x, pf.x);
            p2[1] = pack2(pf.y, pf.y);
            p2[2] = pack2(pf.z, pf.z);
            p2[3] = pack2(pf.w, pf.w);
            #pragma unroll
            for (int i = 0; i < 4; i++) {
                ulonglong2 kv = *(const ulonglong2*)(ks + j * QP + cbase + 16 * i);
                #pragma unroll
                for (int tt = 0; tt < 4; tt++) {
                    O2[tt][2 * i + 0] = fma2(p2[tt], kv.x, O2[tt][2 * i + 0]);
                    O2[tt][2 * i + 1] = fma2(p2[tt], kv.y, O2[tt][2 * i + 1]);
                }
            }
        }
    }

    // ---- epilogue: normalize, write out[b, c, n0+tok] ----
    float rl[4];
    #pragma unroll
    for (int tt = 0; tt < 4; tt++) rl[tt] = 1.0f / l_s[tokg * 4 + tt];

    float* obase = out + (size_t)b * C_ * N_ + n0;
    #pragma unroll
    for (int i = 0; i < 4; i++)
        #pragma unroll
        for (int h = 0; h < 2; h++) {
            int c0 = cbase + 16 * i + 2 * h;
            #pragma unroll
            for (int tt = 0; tt < 4; tt++) {
                float a, bb; unpack2(O2[tt][2 * i + h], a, bb);
                int tok = tokg * 4 + tt;
                obase[(size_t)(c0 + 0) * N_ + tok] = a  * rl[tt];
                obase[(size_t)(c0 + 1) * N_ + tok] = bb * rl[tt];
            }
        }
}

extern "C" void kernel_launch(void* const* d_in, const int* in_sizes, int n_in,
                              void* d_out, int out_size)
{
    const float* feat = (const float*)d_in[0];   // [16, 512, 64, 64]
    const float* mem  = (const float*)d_in[1];   // [2048, 512]
    float* out        = (float*)d_out;
    (void)in_sizes; (void)n_in; (void)out_size;

    const int smem_bytes = SMEM_FLOATS * (int)sizeof(float);   // ~217 KB
    cudaFuncSetAttribute(memattn_fused_f32x2,
                         cudaFuncAttributeMaxDynamicSharedMemorySize, smem_bytes);

    dim3 grid(N_ / TQ, B_);   // 128 x 16
    memattn_fused_f32x2<<<grid, NTHREADS, smem_bytes>>>(feat, mem, out);
}

// round 8
// speedup vs baseline: 1.0407x; 1.0407x over previous
#include <cuda_runtime.h>

// Problem constants
#define B_   16
#define C_   512
#define N_   4096
#define M_   2048
#define TQ   32      // tokens per CTA
#define MC   64      // memory rows per chunk
#define QP   516     // padded smem row stride (floats) for qs/ks
#define STQ  36      // padded stride for transposed score tile St[MC][STQ]
#define NCHUNK (M_ / MC)
#define NTHREADS 256

// smem (floats): qs[TQ][QP] + ks[MC][QP] + St[MC][STQ] + m/l/sc[TQ each]
#define SMEM_FLOATS (TQ*QP + MC*QP + MC*STQ + 3*TQ)

typedef unsigned long long ull;

__device__ __forceinline__ ull fma2(ull a, ull b, ull c) {
    ull d;
    asm("fma.rn.f32x2 %0, %1, %2, %3;" : "=l"(d) : "l"(a), "l"(b), "l"(c));
    return d;
}
__device__ __forceinline__ ull mul2(ull a, ull b) {
    ull d;
    asm("mul.rn.f32x2 %0, %1, %2;" : "=l"(d) : "l"(a), "l"(b));
    return d;
}
__device__ __forceinline__ ull pack2(float x, float y) {
    ull d;
    asm("mov.b64 %0, {%1, %2};" : "=l"(d) : "f"(x), "f"(y));
    return d;
}
__device__ __forceinline__ void unpack2(ull d, float& x, float& y) {
    asm("mov.b64 {%0, %1}, %2;" : "=f"(x), "=f"(y) : "l"(d));
}

__global__ __launch_bounds__(NTHREADS, 1)
void memattn_v3(const float* __restrict__ feat,
                const float* __restrict__ mem,
                float* __restrict__ out)
{
    extern __shared__ float smem[];
    float* qs   = smem;                 // TQ*QP
    float* ks   = qs + TQ * QP;         // MC*QP
    float* St   = ks + MC * QP;         // MC*STQ (scores transposed: [mrow][tok])
    float* m_s  = St + MC * STQ;        // TQ
    float* l_s  = m_s + TQ;             // TQ
    float* sc_s = l_s + TQ;             // TQ

    const int t    = threadIdx.x;
    const int lane = t & 31;
    const int warp = t >> 5;
    const int b    = blockIdx.y;
    const int n0   = blockIdx.x * TQ;

    if (t < TQ) { m_s[t] = -3.0e38f; l_s[t] = 0.0f; }

    // ---- load Q tile: qs[tok][c] = feat[b, c, n0+tok] ----
    const float* fbase = feat + (size_t)b * C_ * N_ + n0;
    #pragma unroll 4
    for (int idx = t; idx < TQ * C_; idx += NTHREADS) {
        int tok = idx & (TQ - 1);
        int c   = idx >> 5;
        qs[tok * QP + c] = fbase[(size_t)c * N_ + tok];
    }

    // ---- GEMM1 mapping: warp=token-group, lane: 8 mrow-groups x 4 kid ----
    const int tg  = warp;          // tokens tg*4 .. +3
    const int mg  = lane & 7;      // mrows mg + 8*j, j=0..7
    const int kid = lane >> 3;     // k in [kid*128, kid*128+128)

    // ---- GEMM2 mapping: 8 tok x 8 col per thread ----
    const int tokg = lane >> 3;                    // tokens tokg*8 .. +7
    const int cb0  = warp * 64 + (lane & 7) * 4;   // cols cb0..+3 and cb0+32..+35

    ull O2[8][4];   // [token][colpair]: 0,1 -> cb0..+3 ; 2,3 -> cb0+32..+35
    #pragma unroll
    for (int a = 0; a < 8; a++)
        #pragma unroll
        for (int c = 0; c < 4; c++) O2[a][c] = 0ull;

    for (int ch = 0; ch < NCHUNK; ch++) {
        __syncthreads();   // prev GEMM2 done with ks/St (and Q-load on ch==0)

        // ---- load K chunk (MC x C) into ks ----
        const float* mbase = mem + (size_t)(ch * MC) * C_;
        #pragma unroll 4
        for (int idx = t; idx < MC * (C_ / 4); idx += NTHREADS) {
            int row = idx >> 7;
            int c4  = idx & 127;
            float4 v = *(const float4*)(mbase + (size_t)row * C_ + c4 * 4);
            *(float4*)(ks + row * QP + c4 * 4) = v;
        }
        __syncthreads();

        // ---- GEMM1: S = Q @ K^T, 4tok x 8mrow tiles, 4-way in-warp k-split ----
        ull acc2[4][8];
        #pragma unroll
        for (int i = 0; i < 4; i++)
            #pragma unroll
            for (int j = 0; j < 8; j++) acc2[i][j] = 0ull;

        const float* qb = qs + (tg * 4) * QP + kid * 128;
        const float* kb = ks + mg * QP + kid * 128;
        #pragma unroll 2
        for (int k = 0; k < 128; k += 4) {
            ulonglong2 qv[4];
            #pragma unroll
            for (int i = 0; i < 4; i++)
                qv[i] = *(const ulonglong2*)(qb + i * QP + k);
            #pragma unroll
            for (int j = 0; j < 8; j++) {
                ulonglong2 kv = *(const ulonglong2*)(kb + j * 8 * QP + k);
                #pragma unroll
                for (int i = 0; i < 4; i++) {
                    acc2[i][j] = fma2(qv[i].x, kv.x, acc2[i][j]);
                    acc2[i][j] = fma2(qv[i].y, kv.y, acc2[i][j]);
                }
            }
        }

        // reduce the 4 k-splits across lane bits 3,4; every lane ends with full sums
        float sred[4][8];
        #pragma unroll
        for (int i = 0; i < 4; i++)
            #pragma unroll
            for (int j = 0; j < 8; j++) {
                float lo, hi; unpack2(acc2[i][j], lo, hi);
                float s = lo + hi;
                s += __shfl_xor_sync(0xffffffffu, s, 8);
                s += __shfl_xor_sync(0xffffffffu, s, 16);
                sred[i][j] = s;
            }
        // kid-lane writes mrow-groups j = 2*kid, 2*kid+1 (partition the duplicates)
        #pragma unroll
        for (int u = 0; u < 2; u++) {
            int jj = kid * 2 + u;
            float4 v = make_float4(sred[0][jj], sred[1][jj], sred[2][jj], sred[3][jj]);
            *(float4*)(St + (mg + 8 * jj) * STQ + tg * 4) = v;
        }
        __syncthreads();

        // ---- online softmax on St columns (per token), 8 lanes/token ----
        {
            int row = t >> 3;          // token
            int g   = t & 7;
            float mx = -3.0e38f;
            #pragma unroll
            for (int j = g; j < MC; j += 8) mx = fmaxf(mx, St[j * STQ + row]);
            mx = fmaxf(mx, __shfl_xor_sync(0xffffffffu, mx, 4));
            mx = fmaxf(mx, __shfl_xor_sync(0xffffffffu, mx, 2));
            mx = fmaxf(mx, __shfl_xor_sync(0xffffffffu, mx, 1));
            float oldm = m_s[row];
            float newm = fmaxf(oldm, mx);
            float sum = 0.0f;
            #pragma unroll
            for (int j = g; j < MC; j += 8) {
                float p = __expf(St[j * STQ + row] - newm);
                St[j * STQ + row] = p;
                sum += p;
            }
            sum += __shfl_xor_sync(0xffffffffu, sum, 4);
            sum += __shfl_xor_sync(0xffffffffu, sum, 2);
            sum += __shfl_xor_sync(0xffffffffu, sum, 1);
            if (g == 0) {
                float sc = __expf(oldm - newm);
                sc_s[row] = sc;
                m_s[row]  = newm;
                l_s[row]  = l_s[row] * sc + sum;
            }
        }
        __syncthreads();

        // ---- GEMM2: O += P @ K  (8 tok x 8 col per thread) ----
        #pragma unroll
        for (int tt = 0; tt < 8; tt++) {
            float sc = sc_s[tokg * 8 + tt];
            ull sc2 = pack2(sc, sc);
            #pragma unroll
            for (int c = 0; c < 4; c++) O2[tt][c] = mul2(O2[tt][c], sc2);
        }
        #pragma unroll 2
        for (int j = 0; j < MC; j++) {
            float4 p0 = *(const float4*)(St + j * STQ + tokg * 8);
            float4 p1 = *(const float4*)(St + j * STQ + tokg * 8 + 4);
            ulonglong2 kva = *(const ulonglong2*)(ks + j * QP + cb0);
            ulonglong2 kvb = *(const ulonglong2*)(ks + j * QP + cb0 + 32);
            float pa[8] = {p0.x, p0.y, p0.z, p0.w, p1.x, p1.y, p1.z, p1.w};
            #pragma unroll
            for (int tt = 0; tt < 8; tt++) {
                ull p2 = pack2(pa[tt], pa[tt]);
                O2[tt][0] = fma2(p2, kva.x, O2[tt][0]);
                O2[tt][1] = fma2(p2, kva.y, O2[tt][1]);
                O2[tt][2] = fma2(p2, kvb.x, O2[tt][2]);
                O2[tt][3] = fma2(p2, kvb.y, O2[tt][3]);
            }
        }
    }

    // ---- epilogue: normalize; thread owns 8 consecutive tokens -> float4 stores ----
    float rl[8];
    #pragma unroll
    for (int tt = 0; tt < 8; tt++) rl[tt] = 1.0f / l_s[tokg * 8 + tt];

    float* obase = out + (size_t)b * C_ * N_ + n0 + tokg * 8;
    #pragma unroll
    for (int cp = 0; cp < 4; cp++) {
        int c0 = cb0 + (cp >> 1) * 32 + (cp & 1) * 2;   // col pair c0, c0+1
        float a[8], bb[8];
        #pragma unroll
        for (int tt = 0; tt < 8; tt++) {
            unpack2(O2[tt][((cp >> 1) << 1) | (cp & 1)], a[tt], bb[tt]);
            a[tt]  *= rl[tt];
            bb[tt] *= rl[tt];
        }
        *(float4*)(obase + (size_t)(c0 + 0) * N_)     = make_float4(a[0], a[1], a[2], a[3]);
        *(float4*)(obase + (size_t)(c0 + 0) * N_ + 4) = make_float4(a[4], a[5], a[6], a[7]);
        *(float4*)(obase + (size_t)(c0 + 1) * N_)     = make_float4(bb[0], bb[1], bb[2], bb[3]);
        *(float4*)(obase + (size_t)(c0 + 1) * N_ + 4) = make_float4(bb[4], bb[5], bb[6], bb[7]);
    }
}

extern "C" void kernel_launch(void* const* d_in, const int* in_sizes, int n_in,
                              void* d_out, int out_size)
{
    const float* feat = (const float*)d_in[0];   // [16, 512, 64, 64]
    const float* mem  = (const float*)d_in[1];   // [2048, 512]
    float* out        = (float*)d_out;
    (void)in_sizes; (void)n_in; (void)out_size;

    const int smem_bytes = SMEM_FLOATS * (int)sizeof(float);   // ~208 KB
    cudaFuncSetAttribute(memattn_v3,
                         cudaFuncAttributeMaxDynamicSharedMemorySize, smem_bytes);

    dim3 grid(N_ / TQ, B_);   // 128 x 16
    memattn_v3<<<grid, NTHREADS, smem_bytes>>>(feat, mem, out);
}

// round 9
// speedup vs baseline: 1.0415x; 1.0008x over previous
#include <cuda_runtime.h>

// Problem constants
#define B_   16
#define C_   512
#define N_   4096
#define M_   2048
#define TQ   32      // tokens per CTA
#define MC   64      // memory rows per chunk
#define QP   516     // padded smem row stride (floats) for qs/ks
#define STQ  36      // padded stride for transposed score tile St[MC][STQ]
#define NCHUNK (M_ / MC)
#define NTHREADS 256

// smem (floats): qs[TQ][QP] + ks[MC][QP] + St[MC][STQ] + m/l/sc[TQ each]
#define SMEM_FLOATS (TQ*QP + MC*QP + MC*STQ + 3*TQ)

typedef unsigned long long ull;

__device__ __forceinline__ ull fma2(ull a, ull b, ull c) {
    ull d;
    asm("fma.rn.f32x2 %0, %1, %2, %3;" : "=l"(d) : "l"(a), "l"(b), "l"(c));
    return d;
}
__device__ __forceinline__ ull mul2(ull a, ull b) {
    ull d;
    asm("mul.rn.f32x2 %0, %1, %2;" : "=l"(d) : "l"(a), "l"(b));
    return d;
}
__device__ __forceinline__ ull pack2(float x, float y) {
    ull d;
    asm("mov.b64 %0, {%1, %2};" : "=l"(d) : "f"(x), "f"(y));
    return d;
}
__device__ __forceinline__ void unpack2(ull d, float& x, float& y) {
    asm("mov.b64 {%0, %1}, %2;" : "=f"(x), "=f"(y) : "l"(d));
}

__global__ __launch_bounds__(NTHREADS, 1)
void memattn_v3(const float* __restrict__ feat,
                const float* __restrict__ mem,
                float* __restrict__ out)
{
    extern __shared__ float smem[];
    float* qs   = smem;                 // TQ*QP
    float* ks   = qs + TQ * QP;         // MC*QP
    float* St   = ks + MC * QP;         // MC*STQ (scores transposed: [mrow][tok])
    float* m_s  = St + MC * STQ;        // TQ
    float* l_s  = m_s + TQ;             // TQ
    float* sc_s = l_s + TQ;             // TQ

    const int t    = threadIdx.x;
    const int lane = t & 31;
    const int warp = t >> 5;
    const int b    = blockIdx.y;
    const int n0   = blockIdx.x * TQ;

    if (t < TQ) { m_s[t] = -3.0e38f; l_s[t] = 0.0f; }

    // ---- load Q tile: qs[tok][c] = feat[b, c, n0+tok] ----
    const float* fbase = feat + (size_t)b * C_ * N_ + n0;
    #pragma unroll 4
    for (int idx = t; idx < TQ * C_; idx += NTHREADS) {
        int tok = idx & (TQ - 1);
        int c   = idx >> 5;
        qs[tok * QP + c] = fbase[(size_t)c * N_ + tok];
    }

    // ---- GEMM1 mapping: warp=token-group, lane: 8 mrow-groups x 4 kid ----
    const int tg  = warp;          // tokens tg*4 .. +3
    const int mg  = lane & 7;      // mrows mg + 8*j, j=0..7
    const int kid = lane >> 3;     // k in [kid*128, kid*128+128)

    // ---- GEMM2 mapping: 8 tok x 8 col per thread ----
    const int tokg = lane >> 3;                    // tokens tokg*8 .. +7
    const int cb0  = warp * 64 + (lane & 7) * 4;   // cols cb0..+3 and cb0+32..+35

    ull O2[8][4];   // [token][colpair]: 0,1 -> cb0..+3 ; 2,3 -> cb0+32..+35
    #pragma unroll
    for (int a = 0; a < 8; a++)
        #pragma unroll
        for (int c = 0; c < 4; c++) O2[a][c] = 0ull;

    for (int ch = 0; ch < NCHUNK; ch++) {
        __syncthreads();   // prev GEMM2 done with ks/St (and Q-load on ch==0)

        // ---- load K chunk (MC x C) into ks ----
        const float* mbase = mem + (size_t)(ch * MC) * C_;
        #pragma unroll 4
        for (int idx = t; idx < MC * (C_ / 4); idx += NTHREADS) {
            int row = idx >> 7;
            int c4  = idx & 127;
            float4 v = *(const float4*)(mbase + (size_t)row * C_ + c4 * 4);
            *(float4*)(ks + row * QP + c4 * 4) = v;
        }
        __syncthreads();

        // ---- GEMM1: S = Q @ K^T, 4tok x 8mrow tiles, 4-way in-warp k-split ----
        ull acc2[4][8];
        #pragma unroll
        for (int i = 0; i < 4; i++)
            #pragma unroll
            for (int j = 0; j < 8; j++) acc2[i][j] = 0ull;

        const float* qb = qs + (tg * 4) * QP + kid * 128;
        const float* kb = ks + mg * QP + kid * 128;
        #pragma unroll 2
        for (int k = 0; k < 128; k += 4) {
            ulonglong2 qv[4];
            #pragma unroll
            for (int i = 0; i < 4; i++)
                qv[i] = *(const ulonglong2*)(qb + i * QP + k);
            #pragma unroll
            for (int j = 0; j < 8; j++) {
                ulonglong2 kv = *(const ulonglong2*)(kb + j * 8 * QP + k);
                #pragma unroll
                for (int i = 0; i < 4; i++) {
                    acc2[i][j] = fma2(qv[i].x, kv.x, acc2[i][j]);
                    acc2[i][j] = fma2(qv[i].y, kv.y, acc2[i][j]);
                }
            }
        }

        // reduce the 4 k-splits across lane bits 3,4; every lane ends with full sums
        float sred[4][8];
        #pragma unroll
        for (int i = 0; i < 4; i++)
            #pragma unroll
            for (int j = 0; j < 8; j++) {
                float lo, hi; unpack2(acc2[i][j], lo, hi);
                float s = lo + hi;
                s += __shfl_xor_sync(0xffffffffu, s, 8);
                s += __shfl_xor_sync(0xffffffffu, s, 16);
                sred[i][j] = s;
            }
        // kid-lane writes mrow-groups j = 2*kid, 2*kid+1 (partition the duplicates)
        #pragma unroll
        for (int u = 0; u < 2; u++) {
            int jj = kid * 2 + u;
            float4 v = make_float4(sred[0][jj], sred[1][jj], sred[2][jj], sred[3][jj]);
            *(float4*)(St + (mg + 8 * jj) * STQ + tg * 4) = v;
        }
        __syncthreads();

        // ---- online softmax on St columns (per token), 8 lanes/token ----
        {
            int row = t >> 3;          // token
            int g   = t & 7;
            float mx = -3.0e38f;
            #pragma unroll
            for (int j = g; j < MC; j += 8) mx = fmaxf(mx, St[j * STQ + row]);
            mx = fmaxf(mx, __shfl_xor_sync(0xffffffffu, mx, 4));
            mx = fmaxf(mx, __shfl_xor_sync(0xffffffffu, mx, 2));
            mx = fmaxf(mx, __shfl_xor_sync(0xffffffffu, mx, 1));
            float oldm = m_s[row];
            float newm = fmaxf(oldm, mx);
            float sum = 0.0f;
            #pragma unroll
            for (int j = g; j < MC; j += 8) {
                float p = __expf(St[j * STQ + row] - newm);
                St[j * STQ + row] = p;
                sum += p;
            }
            sum += __shfl_xor_sync(0xffffffffu, sum, 4);
            sum += __shfl_xor_sync(0xffffffffu, sum, 2);
            sum += __shfl_xor_sync(0xffffffffu, sum, 1);
            if (g == 0) {
                float sc = __expf(oldm - newm);
                sc_s[row] = sc;
                m_s[row]  = newm;
                l_s[row]  = l_s[row] * sc + sum;
            }
        }
        __syncthreads();

        // ---- GEMM2: O += P @ K  (8 tok x 8 col per thread) ----
        #pragma unroll
        for (int tt = 0; tt < 8; tt++) {
            float sc = sc_s[tokg * 8 + tt];
            ull sc2 = pack2(sc, sc);
            #pragma unroll
            for (int c = 0; c < 4; c++) O2[tt][c] = mul2(O2[tt][c], sc2);
        }
        #pragma unroll 2
        for (int j = 0; j < MC; j++) {
            float4 p0 = *(const float4*)(St + j * STQ + tokg * 8);
            float4 p1 = *(const float4*)(St + j * STQ + tokg * 8 + 4);
            ulonglong2 kva = *(const ulonglong2*)(ks + j * QP + cb0);
            ulonglong2 kvb = *(const ulonglong2*)(ks + j * QP + cb0 + 32);
            float pa[8] = {p0.x, p0.y, p0.z, p0.w, p1.x, p1.y, p1.z, p1.w};
            #pragma unroll
            for (int tt = 0; tt < 8; tt++) {
                ull p2 = pack2(pa[tt], pa[tt]);
                O2[tt][0] = fma2(p2, kva.x, O2[tt][0]);
                O2[tt][1] = fma2(p2, kva.y, O2[tt][1]);
                O2[tt][2] = fma2(p2, kvb.x, O2[tt][2]);
                O2[tt][3] = fma2(p2, kvb.y, O2[tt][3]);
            }
        }
    }

    // ---- epilogue: normalize; thread owns 8 consecutive tokens -> float4 stores ----
    float rl[8];
    #pragma unroll
    for (int tt = 0; tt < 8; tt++) rl[tt] = 1.0f / l_s[tokg * 8 + tt];

    float* obase = out + (size_t)b * C_ * N_ + n0 + tokg * 8;
    #pragma unroll
    for (int cp = 0; cp < 4; cp++) {
        int c0 = cb0 + (cp >> 1) * 32 + (cp & 1) * 2;   // col pair c0, c0+1
        float a[8], bb[8];
        #pragma unroll
        for (int tt = 0; tt < 8; tt++) {
            unpack2(O2[tt][((cp >> 1) << 1) | (cp & 1)], a[tt], bb[tt]);
            a[tt]  *= rl[tt];
            bb[tt] *= rl[tt];
        }
        *(float4*)(obase + (size_t)(c0 + 0) * N_)     = make_float4(a[0], a[1], a[2], a[3]);
        *(float4*)(obase + (size_t)(c0 + 0) * N_ + 4) = make_float4(a[4], a[5], a[6], a[7]);
        *(float4*)(obase + (size_t)(c0 + 1) * N_)     = make_float4(bb[0], bb[1], bb[2], bb[3]);
        *(float4*)(obase + (size_t)(c0 + 1) * N_ + 4) = make_float4(bb[4], bb[5], bb[6], bb[7]);
    }
}

extern "C" void kernel_launch(void* const* d_in, const int* in_sizes, int n_in,
                              void* d_out, int out_size)
{
    const float* feat = (const float*)d_in[0];   // [16, 512, 64, 64]
    const float* mem  = (const float*)d_in[1];   // [2048, 512]
    float* out        = (float*)d_out;
    (void)in_sizes; (void)n_in; (void)out_size;

    const int smem_bytes = SMEM_FLOATS * (int)sizeof(float);   // ~208 KB
    cudaFuncSetAttribute(memattn_v3,
                         cudaFuncAttributeMaxDynamicSharedMemorySize, smem_bytes);

    dim3 grid(N_ / TQ, B_);   // 128 x 16
    memattn_v3<<<grid, NTHREADS, smem_bytes>>>(feat, mem, out);
}